// round 9
// baseline (speedup 1.0000x reference)
#include <cuda_runtime.h>

#define C       128
#define ALPHA   0.25f
#define WARPS_PER_BLOCK 8
#define THREADS (WARPS_PER_BLOCK * 32)
#define UNROLL  4
#define GRID_BLOCKS 2368   // 148 SMs * 16 blocks: oversubscribed, self-balancing

// Per-block partials: every replay fully overwrites all entries (no zeroing,
// no atomics, no fences needed). Kernel boundary orders writes vs. finalize.
__device__ float g_partials[GRID_BLOCKS];

__global__ __launch_bounds__(THREADS) void fl_main_kernel(
    const float* __restrict__ preds,
    const int*   __restrict__ labels,
    int n_rows)
{
    const unsigned lane   = threadIdx.x & 31u;
    const unsigned warp   = threadIdx.x >> 5;
    const unsigned gwarp  = blockIdx.x * WARPS_PER_BLOCK + warp;
    const unsigned nwarps = gridDim.x * WARPS_PER_BLOCK;

    __shared__ float partial[WARPS_PER_BLOCK];

    float acc = 0.0f;

    const unsigned n_groups = (unsigned)n_rows / UNROLL;  // 262144 (exact)
    const unsigned lane_off = lane * 4u;
    const unsigned stride   = nwarps * (UNROLL * C);

    unsigned base = gwarp * (UNROLL * C) + lane_off;
    for (unsigned g = gwarp; g < n_groups; g += nwarps, base += stride) {

        // Front-batch 8 independent LDG.128s.
        float4 p[UNROLL];
        int4   l[UNROLL];
        #pragma unroll
        for (int u = 0; u < UNROLL; u++)
            p[u] = *reinterpret_cast<const float4*>(preds + base + u * C);
        #pragma unroll
        for (int u = 0; u < UNROLL; u++)
            l[u] = *reinterpret_cast<const int4*>(labels + base + u * C);

        float    se[UNROLL];
        unsigned lb[UNROLL];
        #pragma unroll
        for (int u = 0; u < UNROLL; u++) {
            se[u] = __expf(p[u].x) + __expf(p[u].y)
                  + __expf(p[u].z) + __expf(p[u].w);
            // One-hot gather: exactly one nonzero term per ROW, so integer
            // sum within the lane, then OR across lanes, is exact.
            lb[u] = (unsigned)(l[u].x * __float_as_int(p[u].x)
                             + l[u].y * __float_as_int(p[u].y)
                             + l[u].z * __float_as_int(p[u].z)
                             + l[u].w * __float_as_int(p[u].w));
        }

        // Cross-lane one-hot gather: single REDUX.OR per row.
        #pragma unroll
        for (int u = 0; u < UNROLL; u++)
            lb[u] = __reduce_or_sync(0xffffffffu, lb[u]);

        // Butterfly sum for sum-of-exp, interleaved across rows for ILP.
        #pragma unroll
        for (int off = 16; off; off >>= 1) {
            #pragma unroll
            for (int u = 0; u < UNROLL; u++)
                se[u] += __shfl_xor_sync(0xffffffffu, se[u], off);
        }

        #pragma unroll
        for (int u = 0; u < UNROLL; u++) {
            const float t1  = se[u];
            const float lbl = __int_as_float((int)lb[u]);   // labeled logit
            const float pgt = __fdividef(__expf(lbl), t1);
            const float om  = 1.0f - pgt;
            acc += ALPHA * om * om * (__logf(t1) - lbl);
        }
    }

    if (lane == 0) partial[warp] = acc;
    __syncthreads();

    // Plain store of the block partial (deterministic overwrite each replay).
    if (threadIdx.x == 0) {
        float s = 0.0f;
        #pragma unroll
        for (int i = 0; i < WARPS_PER_BLOCK; i++) s += partial[i];
        g_partials[blockIdx.x] = s;
    }
}

__global__ __launch_bounds__(THREADS) void fl_finalize_kernel(
    float* __restrict__ out, int n_rows)
{
    __shared__ double s_red[THREADS];

    double d = 0.0;
    for (int i = threadIdx.x; i < GRID_BLOCKS; i += THREADS)
        d += (double)g_partials[i];
    s_red[threadIdx.x] = d;
    __syncthreads();

    #pragma unroll
    for (int s2 = THREADS / 2; s2 > 0; s2 >>= 1) {
        if (threadIdx.x < s2) s_red[threadIdx.x] += s_red[threadIdx.x + s2];
        __syncthreads();
    }
    if (threadIdx.x == 0)
        out[0] = (float)(s_red[0] / (double)n_rows);
}

extern "C" void kernel_launch(void* const* d_in, const int* in_sizes, int n_in,
                              void* d_out, int out_size)
{
    const float* preds  = (const float*)d_in[0];
    const int*   labels = (const int*)d_in[1];
    float* out = (float*)d_out;

    const int n_rows = in_sizes[0] / C;

    fl_main_kernel<<<GRID_BLOCKS, THREADS>>>(preds, labels, n_rows);
    fl_finalize_kernel<<<1, THREADS>>>(out, n_rows);
}

// round 10
// speedup vs baseline: 1.0409x; 1.0409x over previous
#include <cuda_runtime.h>

#define C       128
#define ALPHA   0.25f
#define WARPS_PER_BLOCK 8
#define THREADS (WARPS_PER_BLOCK * 32)
#define UNROLL  4
#define GRID_BLOCKS 2368   // 148 SMs * 16 blocks: oversubscribed, self-balancing

// Accumulator: starts at 0 (static init); finalize resets it to 0 after each
// read, so every graph replay starts from 0. No zero-kernel needed.
__device__ double g_sum = 0.0;

__global__ __launch_bounds__(THREADS) void fl_main_kernel(
    const float* __restrict__ preds,
    const int*   __restrict__ labels,
    int n_rows)
{
    const unsigned lane   = threadIdx.x & 31u;
    const unsigned warp   = threadIdx.x >> 5;
    const unsigned gwarp  = blockIdx.x * WARPS_PER_BLOCK + warp;
    const unsigned nwarps = gridDim.x * WARPS_PER_BLOCK;

    __shared__ float partial[WARPS_PER_BLOCK];

    float acc = 0.0f;

    const unsigned n_groups = (unsigned)n_rows / UNROLL;  // 262144 (exact)
    const unsigned lane_off = lane * 4u;
    const unsigned stride   = nwarps * (UNROLL * C);

    unsigned base = gwarp * (UNROLL * C) + lane_off;
    for (unsigned g = gwarp; g < n_groups; g += nwarps, base += stride) {

        // Front-batch 8 independent LDG.128s.
        float4 p[UNROLL];
        int4   l[UNROLL];
        #pragma unroll
        for (int u = 0; u < UNROLL; u++)
            p[u] = *reinterpret_cast<const float4*>(preds + base + u * C);
        #pragma unroll
        for (int u = 0; u < UNROLL; u++)
            l[u] = *reinterpret_cast<const int4*>(labels + base + u * C);

        float    se[UNROLL];
        unsigned lb[UNROLL];
        #pragma unroll
        for (int u = 0; u < UNROLL; u++) {
            se[u] = __expf(p[u].x) + __expf(p[u].y)
                  + __expf(p[u].z) + __expf(p[u].w);
            // One-hot gather: exactly one nonzero term per ROW, so integer
            // sum within the lane, then OR across lanes, is exact.
            lb[u] = (unsigned)(l[u].x * __float_as_int(p[u].x)
                             + l[u].y * __float_as_int(p[u].y)
                             + l[u].z * __float_as_int(p[u].z)
                             + l[u].w * __float_as_int(p[u].w));
        }

        // Cross-lane one-hot gather: single REDUX.OR per row.
        #pragma unroll
        for (int u = 0; u < UNROLL; u++)
            lb[u] = __reduce_or_sync(0xffffffffu, lb[u]);

        // Butterfly sum for sum-of-exp, interleaved across rows for ILP.
        #pragma unroll
        for (int off = 16; off; off >>= 1) {
            #pragma unroll
            for (int u = 0; u < UNROLL; u++)
                se[u] += __shfl_xor_sync(0xffffffffu, se[u], off);
        }

        #pragma unroll
        for (int u = 0; u < UNROLL; u++) {
            const float t1  = se[u];
            const float lbl = __int_as_float((int)lb[u]);   // labeled logit
            const float pgt = __fdividef(__expf(lbl), t1);
            const float om  = 1.0f - pgt;
            acc += ALPHA * om * om * (__logf(t1) - lbl);
        }
    }

    if (lane == 0) partial[warp] = acc;
    __syncthreads();

    // One fp64 atomic per block (2368 single-address atomics, ~negligible).
    if (threadIdx.x == 0) {
        float s = 0.0f;
        #pragma unroll
        for (int i = 0; i < WARPS_PER_BLOCK; i++) s += partial[i];
        atomicAdd(&g_sum, (double)s);
    }
}

__global__ void fl_finalize_kernel(float* __restrict__ out, int n_rows)
{
    const double s = g_sum;
    out[0] = (float)(s / (double)n_rows);
    g_sum = 0.0;   // reset for the next replay (stream order protects this)
}

extern "C" void kernel_launch(void* const* d_in, const int* in_sizes, int n_in,
                              void* d_out, int out_size)
{
    const float* preds  = (const float*)d_in[0];
    const int*   labels = (const int*)d_in[1];
    float* out = (float*)d_out;

    const int n_rows = in_sizes[0] / C;

    fl_main_kernel<<<GRID_BLOCKS, THREADS>>>(preds, labels, n_rows);
    fl_finalize_kernel<<<1, 1>>>(out, n_rows);
}